// round 2
// baseline (speedup 1.0000x reference)
#include <cuda_runtime.h>
#include <cstdint>
#include <float.h>

// Problem constants
#define BB   2
#define NN   1024
#define MM   4
#define CLL  1024
#define JJ   (MM*CLL)     // 4096
#define DIMM 1024
#define HH   8
#define HD   128

// Scratch (device globals -- allocation-free rule)
__device__ float g_q[BB*NN*DIMM];        // 8 MB   q projection [B*N, DIM]
__device__ float g_kv[BB*JJ*2*DIMM];     // 64 MB  kv projection [B*J, 2*DIM]
__device__ float g_ao[BB*NN*DIMM];       // 8 MB   attention output [B*N, DIM]

// ----------------------------------------------------------------------------
// SGEMM: C[M,N] = A[M,K] @ B[N,K]^T (+bias), all row-major, C has stride ldc.
// 128x128 block tile, BK=16, 256 threads, 8x8 micro tile.
// ----------------------------------------------------------------------------
#define GBM 128
#define GBN 128
#define GBK 16

__global__ __launch_bounds__(256, 2)
void sgemm_nt(const float* __restrict__ A, const float* __restrict__ Bm,
              const float* __restrict__ bias, float* __restrict__ C,
              int Mdim, int Ndim, int K, int ldc)
{
    __shared__ float As[GBK][GBM + 4];
    __shared__ float Bs[GBK][GBN + 4];

    const int tid = threadIdx.x;
    const int ty  = tid >> 4;      // 0..15, rows ty*8..+7
    const int tx  = tid & 15;      // 0..15, cols tx*8..+7
    const int m0  = blockIdx.y * GBM;
    const int n0  = blockIdx.x * GBN;

    float acc[8][8];
#pragma unroll
    for (int i = 0; i < 8; i++)
#pragma unroll
        for (int j = 0; j < 8; j++) acc[i][j] = 0.f;

    const float* Ap = A + (long)m0 * K;
    const float* Bp = Bm + (long)n0 * K;

    for (int k0 = 0; k0 < K; k0 += GBK) {
        // Load 128x16 tiles of A and B, store transposed [k][m]
#pragma unroll
        for (int p = 0; p < 2; p++) {
            int li = tid + p * 256;        // float4 index (512 per tile)
            int r  = li >> 2;              // 0..127
            int c  = (li & 3) << 2;        // 0,4,8,12
            float4 va = *(const float4*)(Ap + (long)r * K + k0 + c);
            As[c + 0][r] = va.x; As[c + 1][r] = va.y;
            As[c + 2][r] = va.z; As[c + 3][r] = va.w;
            float4 vb = *(const float4*)(Bp + (long)r * K + k0 + c);
            Bs[c + 0][r] = vb.x; Bs[c + 1][r] = vb.y;
            Bs[c + 2][r] = vb.z; Bs[c + 3][r] = vb.w;
        }
        __syncthreads();

#pragma unroll
        for (int kk = 0; kk < GBK; kk++) {
            float a[8], b[8];
#pragma unroll
            for (int i = 0; i < 8; i++) a[i] = As[kk][ty * 8 + i];
#pragma unroll
            for (int j = 0; j < 8; j++) b[j] = Bs[kk][tx * 8 + j];
#pragma unroll
            for (int i = 0; i < 8; i++)
#pragma unroll
                for (int j = 0; j < 8; j++) acc[i][j] += a[i] * b[j];
        }
        __syncthreads();
    }

    // Epilogue
#pragma unroll
    for (int i = 0; i < 8; i++) {
        float* Crow = C + (long)(m0 + ty * 8 + i) * ldc + n0 + tx * 8;
#pragma unroll
        for (int j = 0; j < 8; j++) {
            float v = acc[i][j];
            if (bias) v += bias[n0 + tx * 8 + j];
            Crow[j] = v;
        }
    }
}

// ----------------------------------------------------------------------------
// Flash attention: per (b, h, q-tile of 32), loop over J=4096 in tiles of 64.
// 256 threads. Online softmax. K stored transposed in smem.
// Masks arrive as int32 (harness converts bool -> int32).
// ----------------------------------------------------------------------------
#define BQ 32
#define BJ 64
#define KT_PAD 65
#define S_PAD  65

// smem floats: Qs 32*128 + Kt 128*65 + Vs 64*128 + Ssm 32*65 + 4*32
#define ATTN_SMEM_FLOATS (BQ*HD + HD*KT_PAD + BJ*HD + BQ*S_PAD + 4*BQ)
#define ATTN_SMEM_BYTES  (ATTN_SMEM_FLOATS * 4)

__global__ __launch_bounds__(256, 2)
void attn_kernel(const float* __restrict__ q, const float* __restrict__ kv,
                 const float* __restrict__ ds, const int* __restrict__ mask,
                 const int* __restrict__ cmask, const float* __restrict__ betap,
                 float* __restrict__ o)
{
    extern __shared__ float sm[];
    float* Qs   = sm;                      // [BQ][HD]
    float* Kt   = Qs + BQ * HD;            // [HD][KT_PAD]   (K transposed)
    float* Vs   = Kt + HD * KT_PAD;        // [BJ][HD]
    float* Ssm  = Vs + BJ * HD;            // [BQ][S_PAD]
    float* m_s  = Ssm + BQ * S_PAD;        // [BQ]
    float* l_s  = m_s + BQ;                // [BQ]
    float* f_s  = l_s + BQ;                // [BQ]
    float* rowm = f_s + BQ;                // [BQ]

    const int tid = threadIdx.x;
    const int b   = blockIdx.z;
    const int h   = blockIdx.y;
    const int q0  = blockIdx.x * BQ;
    const float beta  = *betap;
    const float scale = 0.03125f;          // 1/sqrt(1024)

    // Load Q tile (32x128) and init per-row state
#pragma unroll
    for (int p = 0; p < 4; p++) {
        int li = tid + p * 256;            // f4 index (1024 total)
        int r  = li >> 5;                  // 0..31
        int c  = (li & 31) << 2;           // 0..124
        float4 v = *(const float4*)(q + (long)(b * NN + q0 + r) * DIMM + h * HD + c);
        *(float4*)&Qs[r * HD + c] = v;
    }
    if (tid < BQ) {
        m_s[tid]  = -FLT_MAX;
        l_s[tid]  = 0.f;
        rowm[tid] = (mask[b * NN + q0 + tid] != 0) ? 1.f : 0.f;
    }
    __syncthreads();

    // thread mappings
    const int wr  = tid >> 5;              // warp id: rows wr*4..+3 (S, softmax, PV)
    const int sc  = tid & 31;              // S cols sc*2, sc*2+1 ; PV cols sc*4..+3
    const int sr0 = wr * 4;

    float O[4][4];
#pragma unroll
    for (int i = 0; i < 4; i++)
#pragma unroll
        for (int j = 0; j < 4; j++) O[i][j] = 0.f;

    for (int j0 = 0; j0 < JJ; j0 += BJ) {
        // ---- Load K (transposed) and V tiles ----
#pragma unroll
        for (int p = 0; p < 8; p++) {
            int li = tid + p * 256;        // f4 index (2048 total)
            int jr = li >> 5;              // 0..63
            int c  = (li & 31) << 2;       // 0..124
            long base = (long)(b * JJ + j0 + jr) * (2 * DIMM) + h * HD + c;
            float4 kvv = *(const float4*)(kv + base);
            Kt[(c + 0) * KT_PAD + jr] = kvv.x;
            Kt[(c + 1) * KT_PAD + jr] = kvv.y;
            Kt[(c + 2) * KT_PAD + jr] = kvv.z;
            Kt[(c + 3) * KT_PAD + jr] = kvv.w;
            float4 vv = *(const float4*)(kv + base + DIMM);
            *(float4*)&Vs[jr * HD + c] = vv;
        }
        __syncthreads();

        // ---- S = Q @ K^T (each thread: 4 rows x 2 cols) ----
        {
            const int c0 = sc * 2;
            float accS[4][2];
#pragma unroll
            for (int i = 0; i < 4; i++) { accS[i][0] = 0.f; accS[i][1] = 0.f; }
#pragma unroll 8
            for (int k = 0; k < HD; k++) {
                float b0 = Kt[k * KT_PAD + c0];
                float b1 = Kt[k * KT_PAD + c0 + 1];
#pragma unroll
                for (int i = 0; i < 4; i++) {
                    float a = Qs[(sr0 + i) * HD + k];
                    accS[i][0] += a * b0;
                    accS[i][1] += a * b1;
                }
            }
            int jc0 = j0 + c0;
            float sim0 = ds[b * MM + (jc0 >> 10)] * beta;
            float sim1 = ds[b * MM + ((jc0 + 1) >> 10)] * beta;
            bool cm0 = cmask[b * JJ + jc0] != 0;
            bool cm1 = cmask[b * JJ + jc0 + 1] != 0;
#pragma unroll
            for (int i = 0; i < 4; i++) {
                bool rm = rowm[sr0 + i] > 0.5f;
                float v0 = (rm && cm0) ? accS[i][0] * scale + sim0 : -FLT_MAX;
                float v1 = (rm && cm1) ? accS[i][1] * scale + sim1 : -FLT_MAX;
                Ssm[(sr0 + i) * S_PAD + c0]     = v0;
                Ssm[(sr0 + i) * S_PAD + c0 + 1] = v1;
            }
        }
        __syncthreads();

        // ---- Online softmax (warp w owns rows w*4..+3; 8 lanes per row) ----
        {
            const int l   = tid & 31;
            const int row = wr * 4 + (l >> 3);
            const int cc  = (l & 7) * 8;
            float* Srow = &Ssm[row * S_PAD];
            float mx = -FLT_MAX;
#pragma unroll
            for (int c = 0; c < 8; c++) mx = fmaxf(mx, Srow[cc + c]);
#pragma unroll
            for (int off = 1; off < 8; off <<= 1)
                mx = fmaxf(mx, __shfl_xor_sync(0xffffffffu, mx, off));
            float mold = m_s[row];
            float mnew = fmaxf(mold, mx);
            float sum = 0.f;
#pragma unroll
            for (int c = 0; c < 8; c++) {
                float p = __expf(Srow[cc + c] - mnew);
                Srow[cc + c] = p;
                sum += p;
            }
#pragma unroll
            for (int off = 1; off < 8; off <<= 1)
                sum += __shfl_xor_sync(0xffffffffu, sum, off);
            if ((l & 7) == 0) {
                float f = __expf(mold - mnew);
                l_s[row] = l_s[row] * f + sum;
                m_s[row] = mnew;
                f_s[row] = f;
            }
        }
        __syncthreads();

        // ---- Rescale O, then O += P @ V (each thread: 4 rows x 4 cols) ----
        {
            float fr[4];
#pragma unroll
            for (int i = 0; i < 4; i++) fr[i] = f_s[sr0 + i];
#pragma unroll
            for (int i = 0; i < 4; i++)
#pragma unroll
                for (int j = 0; j < 4; j++) O[i][j] *= fr[i];

#pragma unroll 4
            for (int j = 0; j < BJ; j++) {
                float4 v = *(float4*)&Vs[j * HD + sc * 4];
#pragma unroll
                for (int i = 0; i < 4; i++) {
                    float p = Ssm[(sr0 + i) * S_PAD + j];
                    O[i][0] += p * v.x;
                    O[i][1] += p * v.y;
                    O[i][2] += p * v.z;
                    O[i][3] += p * v.w;
                }
            }
        }
        __syncthreads();
    }

    // ---- Finalize: O /= l, write out ----
#pragma unroll
    for (int i = 0; i < 4; i++) {
        float inv = 1.f / l_s[sr0 + i];
        float4 v;
        v.x = O[i][0] * inv; v.y = O[i][1] * inv;
        v.z = O[i][2] * inv; v.w = O[i][3] * inv;
        *(float4*)&o[(long)(b * NN + q0 + sr0 + i) * DIMM + h * HD + sc * 4] = v;
    }
}

// ----------------------------------------------------------------------------
extern "C" void kernel_launch(void* const* d_in, const int* in_sizes, int n_in,
                              void* d_out, int out_size)
{
    const float* x     = (const float*)d_in[0];
    const float* ctx   = (const float*)d_in[1];
    const float* dsim  = (const float*)d_in[2];
    const int*   mask  = (const int*)d_in[3];
    const int*   cmask = (const int*)d_in[4];
    const float* Wq    = (const float*)d_in[5];
    const float* Wkv   = (const float*)d_in[6];
    const float* beta  = (const float*)d_in[7];
    const float* Wout  = (const float*)d_in[8];
    const float* bout  = (const float*)d_in[9];
    float* out = (float*)d_out;

    float *qp, *kvp, *aop;
    cudaGetSymbolAddress((void**)&qp,  g_q);
    cudaGetSymbolAddress((void**)&kvp, g_kv);
    cudaGetSymbolAddress((void**)&aop, g_ao);

    cudaFuncSetAttribute(attn_kernel, cudaFuncAttributeMaxDynamicSharedMemorySize,
                         ATTN_SMEM_BYTES);

    // 1) q = x @ Wq^T : [2048,1024] = [2048,1024] x [1024,1024]^T
    sgemm_nt<<<dim3(DIMM / GBN, (BB * NN) / GBM), 256>>>(
        x, Wq, nullptr, qp, BB * NN, DIMM, DIMM, DIMM);

    // 2) kv = ctx @ Wkv^T : [8192,2048] = [8192,1024] x [2048,1024]^T
    sgemm_nt<<<dim3((2 * DIMM) / GBN, (BB * JJ) / GBM), 256>>>(
        ctx, Wkv, nullptr, kvp, BB * JJ, 2 * DIMM, DIMM, 2 * DIMM);

    // 3) attention
    attn_kernel<<<dim3(NN / BQ, HH, BB), 256, ATTN_SMEM_BYTES>>>(
        qp, kvp, dsim, mask, cmask, beta, aop);

    // 4) out = ao @ Wout^T + bout
    sgemm_nt<<<dim3(DIMM / GBN, (BB * NN) / GBM), 256>>>(
        aop, Wout, bout, out, BB * NN, DIMM, DIMM, DIMM);
}

// round 4
// speedup vs baseline: 1.5935x; 1.5935x over previous
#include <cuda_runtime.h>
#include <cuda_bf16.h>
#include <cstdint>
#include <float.h>

typedef __nv_bfloat16 bf16;

// Problem constants
#define BB    2
#define NN    1024
#define MDOC  4
#define JJ    4096
#define DIMM  1024
#define HH    8
#define HD    128

// ---------------------------------------------------------------------------
// Device-global scratch (allocation-free rule)
// ---------------------------------------------------------------------------
__device__ bf16 g_xh[2048*1024],  g_xl[2048*1024];
__device__ bf16 g_ch[8192*1024],  g_cl[8192*1024];
__device__ bf16 g_Wqh[1024*1024], g_Wql[1024*1024];
__device__ bf16 g_Wkvh[2048*1024],g_Wkvl[2048*1024];
__device__ bf16 g_Woh[1024*1024], g_Wol[1024*1024];
__device__ bf16 g_qh[2048*1024],  g_ql[2048*1024];   // [b,h,n,d]
__device__ bf16 g_kh[8388608],    g_kl[8388608];     // [b,h,j,d]
__device__ bf16 g_vh[8388608],    g_vl[8388608];     // [b,h,j,d]
__device__ bf16 g_aoh[2048*1024], g_aol[2048*1024];  // [b*n, dim]

// ---------------------------------------------------------------------------
// mma.m16n8k16 bf16 helper
// ---------------------------------------------------------------------------
__device__ __forceinline__ void mma16816(float* c, const uint32_t* a, const uint32_t* b) {
    asm volatile(
        "mma.sync.aligned.m16n8k16.row.col.f32.bf16.bf16.f32 "
        "{%0,%1,%2,%3}, {%4,%5,%6,%7}, {%8,%9}, {%0,%1,%2,%3};\n"
        : "+f"(c[0]), "+f"(c[1]), "+f"(c[2]), "+f"(c[3])
        : "r"(a[0]), "r"(a[1]), "r"(a[2]), "r"(a[3]), "r"(b[0]), "r"(b[1]));
}

__device__ __forceinline__ void split2(float v, bf16& h, bf16& l) {
    h = __float2bfloat16(v);
    l = __float2bfloat16(v - __bfloat162float(h));
}

// ---------------------------------------------------------------------------
// fp32 -> (hi, lo) bf16 split conversion
// ---------------------------------------------------------------------------
__global__ void split_kernel(const float* __restrict__ in, bf16* __restrict__ hi,
                             bf16* __restrict__ lo, int n4)
{
    int i = blockIdx.x * blockDim.x + threadIdx.x;
    if (i >= n4) return;
    float4 v = ((const float4*)in)[i];
    bf16 h0,h1,h2,h3,l0,l1,l2,l3;
    split2(v.x,h0,l0); split2(v.y,h1,l1); split2(v.z,h2,l2); split2(v.w,h3,l3);
    __nv_bfloat162 a,b;
    a.x=h0; a.y=h1; b.x=h2; b.y=h3;
    *(__nv_bfloat162*)&hi[4*i]   = a;
    *(__nv_bfloat162*)&hi[4*i+2] = b;
    a.x=l0; a.y=l1; b.x=l2; b.y=l3;
    *(__nv_bfloat162*)&lo[4*i]   = a;
    *(__nv_bfloat162*)&lo[4*i+2] = b;
}

// ---------------------------------------------------------------------------
// Split-bf16 GEMM: C[M,N] = A[M,K] @ B[N,K]^T   (fp32-equivalent precision)
// Block 128x64, BK=32, 256 threads, warp tile 32x32.
// MODE 0: fp32 out + bias. MODE 1: q split head-major. MODE 2: kv split.
// ---------------------------------------------------------------------------
#define TM 128
#define TN 64
#define TBK 32
#define PSTR 40          // smem row stride (bf16): 32 + 8 pad

template<int MODE>
__global__ __launch_bounds__(256, 2)
void gemm_split(const bf16* __restrict__ Ah, const bf16* __restrict__ Al,
                const bf16* __restrict__ Bh, const bf16* __restrict__ Bl,
                int K, float* __restrict__ C, int ldc,
                const float* __restrict__ bias,
                bf16* __restrict__ O1h, bf16* __restrict__ O1l,
                bf16* __restrict__ O2h, bf16* __restrict__ O2l)
{
    __shared__ bf16 sAh[TM*PSTR], sAl[TM*PSTR], sBh[TN*PSTR], sBl[TN*PSTR];

    const int tid  = threadIdx.x;
    const int lane = tid & 31, w = tid >> 5;
    const int g = lane >> 2, p = lane & 3;
    const int mw = w & 3, nw = w >> 1 & 0;   // placeholder; real below
    const int mwr = (w & 3) * 32;            // warp row base
    const int nwr = (w >> 2) * 32;           // warp col base
    const int m0 = blockIdx.y * TM, n0 = blockIdx.x * TN;
    (void)mw; (void)nw;

    float acc[2][4][4];
#pragma unroll
    for (int a = 0; a < 2; a++)
#pragma unroll
        for (int b = 0; b < 4; b++)
#pragma unroll
            for (int c = 0; c < 4; c++) acc[a][b][c] = 0.f;

    for (int k0 = 0; k0 < K; k0 += TBK) {
#pragma unroll
        for (int i = 0; i < 2; i++) {
            int li = tid + i * 256;
            int r = li >> 2, c = li & 3;
            *(uint4*)&sAh[r*PSTR + 8*c] = *(const uint4*)&Ah[(size_t)(m0+r)*K + k0 + 8*c];
            *(uint4*)&sAl[r*PSTR + 8*c] = *(const uint4*)&Al[(size_t)(m0+r)*K + k0 + 8*c];
        }
        {
            int r = tid >> 2, c = tid & 3;
            *(uint4*)&sBh[r*PSTR + 8*c] = *(const uint4*)&Bh[(size_t)(n0+r)*K + k0 + 8*c];
            *(uint4*)&sBl[r*PSTR + 8*c] = *(const uint4*)&Bl[(size_t)(n0+r)*K + k0 + 8*c];
        }
        __syncthreads();

#pragma unroll
        for (int ks = 0; ks < 2; ks++) {
            const int kb = ks * 16;
            uint32_t ah[2][4], al[2][4];
#pragma unroll
            for (int mt = 0; mt < 2; mt++) {
                int rb = mwr + mt * 16;
                ah[mt][0] = *(uint32_t*)&sAh[(rb+g  )*PSTR + kb + 2*p    ];
                ah[mt][1] = *(uint32_t*)&sAh[(rb+g+8)*PSTR + kb + 2*p    ];
                ah[mt][2] = *(uint32_t*)&sAh[(rb+g  )*PSTR + kb + 2*p + 8];
                ah[mt][3] = *(uint32_t*)&sAh[(rb+g+8)*PSTR + kb + 2*p + 8];
                al[mt][0] = *(uint32_t*)&sAl[(rb+g  )*PSTR + kb + 2*p    ];
                al[mt][1] = *(uint32_t*)&sAl[(rb+g+8)*PSTR + kb + 2*p    ];
                al[mt][2] = *(uint32_t*)&sAl[(rb+g  )*PSTR + kb + 2*p + 8];
                al[mt][3] = *(uint32_t*)&sAl[(rb+g+8)*PSTR + kb + 2*p + 8];
            }
#pragma unroll
            for (int nt = 0; nt < 4; nt++) {
                int nb = nwr + nt * 8 + g;
                uint32_t bh[2], bl[2];
                bh[0] = *(uint32_t*)&sBh[nb*PSTR + kb + 2*p    ];
                bh[1] = *(uint32_t*)&sBh[nb*PSTR + kb + 2*p + 8];
                bl[0] = *(uint32_t*)&sBl[nb*PSTR + kb + 2*p    ];
                bl[1] = *(uint32_t*)&sBl[nb*PSTR + kb + 2*p + 8];
#pragma unroll
                for (int mt = 0; mt < 2; mt++) {
                    mma16816(acc[mt][nt], ah[mt], bh);
                    mma16816(acc[mt][nt], ah[mt], bl);
                    mma16816(acc[mt][nt], al[mt], bh);
                }
            }
        }
        __syncthreads();
    }

    // Epilogue
#pragma unroll
    for (int mt = 0; mt < 2; mt++)
#pragma unroll
    for (int nt = 0; nt < 4; nt++)
#pragma unroll
    for (int half = 0; half < 2; half++) {
        int rm = m0 + mwr + mt*16 + g + half*8;
        int cg = n0 + nwr + nt*8 + 2*p;
        float v0 = acc[mt][nt][half*2];
        float v1 = acc[mt][nt][half*2 + 1];
        if (MODE == 0) {
            v0 += bias[cg]; v1 += bias[cg+1];
            float2 f2; f2.x = v0; f2.y = v1;
            *(float2*)&C[(size_t)rm*ldc + cg] = f2;
        } else if (MODE == 1) {
            int b = rm >> 10, n = rm & 1023;
            int hh = cg >> 7, d = cg & 127;
            size_t idx = (((size_t)(b*HH + hh))*NN + n)*HD + d;
            bf16 h0,h1,l0,l1; split2(v0,h0,l0); split2(v1,h1,l1);
            __nv_bfloat162 t;
            t.x=h0; t.y=h1; *(__nv_bfloat162*)&O1h[idx] = t;
            t.x=l0; t.y=l1; *(__nv_bfloat162*)&O1l[idx] = t;
        } else {
            int b = rm >> 12, j = rm & 4095;
            int cc = cg;
            bf16 *dh, *dl;
            if (cc < 1024) { dh = O1h; dl = O1l; }
            else           { cc -= 1024; dh = O2h; dl = O2l; }
            int hh = cc >> 7, d = cc & 127;
            size_t idx = (((size_t)(b*HH + hh))*JJ + j)*HD + d;
            bf16 h0,h1,l0,l1; split2(v0,h0,l0); split2(v1,h1,l1);
            __nv_bfloat162 t;
            t.x=h0; t.y=h1; *(__nv_bfloat162*)&dh[idx] = t;
            t.x=l0; t.y=l1; *(__nv_bfloat162*)&dl[idx] = t;
        }
    }
}

// ---------------------------------------------------------------------------
// Flash attention with split-bf16 mma. BQ=64, BJ=32, 256 threads.
// ---------------------------------------------------------------------------
#define AQ 64
#define AJ 32
#define QSTR 136         // 128 + 8 pad (bf16)
#define VSTR 40          // 32 + 8 pad (bf16)
#define SSTR 40          // fp32 stride for S

#define ATTN_SMEM ((2*AQ*QSTR + 2*AJ*QSTR + 2*HD*VSTR + 2*AQ*VSTR)*2 + AQ*SSTR*4 + 320*4)

__global__ __launch_bounds__(256, 2)
void attn_mma(const bf16* __restrict__ qh, const bf16* __restrict__ ql,
              const bf16* __restrict__ kh, const bf16* __restrict__ kl,
              const bf16* __restrict__ vh, const bf16* __restrict__ vl,
              const float* __restrict__ ds, const int* __restrict__ mask,
              const int* __restrict__ cmask, const float* __restrict__ betap,
              bf16* __restrict__ aoh, bf16* __restrict__ aol)
{
    extern __shared__ char smem[];
    bf16* sQh = (bf16*)smem;
    bf16* sQl = sQh + AQ*QSTR;
    bf16* sKh = sQl + AQ*QSTR;
    bf16* sKl = sKh + AJ*QSTR;
    bf16* sVh = sKl + AJ*QSTR;        // V transposed: [d][j]
    bf16* sVl = sVh + HD*VSTR;
    float* sS = (float*)(sVl + HD*VSTR);
    bf16* sPh = (bf16*)(sS + AQ*SSTR);
    bf16* sPl = sPh + AQ*VSTR;
    float* st  = (float*)(sPl + AQ*VSTR);
    float* s_rok = st;          // 64
    float* s_sim = st + 64;     // 32
    float* s_cok = st + 96;     // 32
    float* s_m   = st + 128;    // 64
    float* s_l   = st + 192;    // 64
    float* s_f   = st + 256;    // 64

    const int tid  = threadIdx.x;
    const int lane = tid & 31, w = tid >> 5;
    const int g = lane >> 2, p = lane & 3;
    const int b = blockIdx.z, h = blockIdx.y, q0 = blockIdx.x * AQ;
    const float beta  = *betap;
    const float scale = 0.03125f;    // 1024^-0.5

    const size_t qbase  = (((size_t)(b*HH + h))*NN + q0)*HD;
    const size_t kvbase = ((size_t)(b*HH + h))*JJ*HD;

    // Load Q tile
#pragma unroll
    for (int i = 0; i < 4; i++) {
        int li = tid + i * 256;
        int r = li >> 4, cc = li & 15;
        *(uint4*)&sQh[r*QSTR + 8*cc] = *(const uint4*)&qh[qbase + (size_t)r*HD + 8*cc];
        *(uint4*)&sQl[r*QSTR + 8*cc] = *(const uint4*)&ql[qbase + (size_t)r*HD + 8*cc];
    }
    if (tid < AQ) {
        s_rok[tid] = (mask[b*NN + q0 + tid] != 0) ? 1.f : 0.f;
        s_m[tid] = -FLT_MAX;
        s_l[tid] = 0.f;
    }
    __syncthreads();

    const int rbase = (w & 3) * 16;   // row base (S and PV)
    const int snb   = (w >> 2) * 16;  // S col base
    const int dnb   = (w >> 2) * 64;  // PV col base

    float O[8][4];
#pragma unroll
    for (int a = 0; a < 8; a++)
#pragma unroll
        for (int c = 0; c < 4; c++) O[a][c] = 0.f;

    for (int j0 = 0; j0 < JJ; j0 += AJ) {
        // ---- load K tile + V^T tile ----
#pragma unroll
        for (int i = 0; i < 2; i++) {
            int li = tid + i * 256;
            int r = li >> 4, cc = li & 15;
            size_t src = kvbase + (size_t)(j0 + r)*HD + 8*cc;
            *(uint4*)&sKh[r*QSTR + 8*cc] = *(const uint4*)&kh[src];
            *(uint4*)&sKl[r*QSTR + 8*cc] = *(const uint4*)&kl[src];
            uint4 vv = *(const uint4*)&vh[src];
            bf16* e = (bf16*)&vv;
#pragma unroll
            for (int t = 0; t < 8; t++) sVh[(8*cc + t)*VSTR + r] = e[t];
            uint4 vw = *(const uint4*)&vl[src];
            bf16* e2 = (bf16*)&vw;
#pragma unroll
            for (int t = 0; t < 8; t++) sVl[(8*cc + t)*VSTR + r] = e2[t];
        }
        if (tid < AJ) {
            int jc = j0 + tid;
            s_sim[tid] = ds[b*MDOC + (jc >> 10)] * beta;
            s_cok[tid] = (cmask[b*JJ + jc] != 0) ? 1.f : 0.f;
        }
        __syncthreads();

        // ---- S = Q @ K^T (warp: 16 rows x 16 cols, 3-mma split) ----
        float SA[2][4];
#pragma unroll
        for (int nt = 0; nt < 2; nt++)
#pragma unroll
            for (int c = 0; c < 4; c++) SA[nt][c] = 0.f;
#pragma unroll
        for (int ks = 0; ks < 8; ks++) {
            const int kb = ks * 16;
            uint32_t ah[4], al[4];
            ah[0] = *(uint32_t*)&sQh[(rbase+g  )*QSTR + kb + 2*p    ];
            ah[1] = *(uint32_t*)&sQh[(rbase+g+8)*QSTR + kb + 2*p    ];
            ah[2] = *(uint32_t*)&sQh[(rbase+g  )*QSTR + kb + 2*p + 8];
            ah[3] = *(uint32_t*)&sQh[(rbase+g+8)*QSTR + kb + 2*p + 8];
            al[0] = *(uint32_t*)&sQl[(rbase+g  )*QSTR + kb + 2*p    ];
            al[1] = *(uint32_t*)&sQl[(rbase+g+8)*QSTR + kb + 2*p    ];
            al[2] = *(uint32_t*)&sQl[(rbase+g  )*QSTR + kb + 2*p + 8];
            al[3] = *(uint32_t*)&sQl[(rbase+g+8)*QSTR + kb + 2*p + 8];
#pragma unroll
            for (int nt = 0; nt < 2; nt++) {
                int nb = snb + nt*8 + g;
                uint32_t bh[2], bl[2];
                bh[0] = *(uint32_t*)&sKh[nb*QSTR + kb + 2*p    ];
                bh[1] = *(uint32_t*)&sKh[nb*QSTR + kb + 2*p + 8];
                bl[0] = *(uint32_t*)&sKl[nb*QSTR + kb + 2*p    ];
                bl[1] = *(uint32_t*)&sKl[nb*QSTR + kb + 2*p + 8];
                mma16816(SA[nt], ah, bh);
                mma16816(SA[nt], ah, bl);
                mma16816(SA[nt], al, bh);
            }
        }
        // store S with scale + bias + mask
#pragma unroll
        for (int nt = 0; nt < 2; nt++)
#pragma unroll
        for (int half = 0; half < 2; half++) {
            int row = rbase + g + half*8;
            int col = snb + nt*8 + 2*p;
            float okr = s_rok[row];
            float v0 = SA[nt][half*2]     * scale + s_sim[col];
            float v1 = SA[nt][half*2 + 1] * scale + s_sim[col+1];
            bool ok0 = (okr > 0.5f) && (s_cok[col]   > 0.5f);
            bool ok1 = (okr > 0.5f) && (s_cok[col+1] > 0.5f);
            sS[row*SSTR + col]     = ok0 ? v0 : -FLT_MAX;
            sS[row*SSTR + col + 1] = ok1 ? v1 : -FLT_MAX;
        }
        __syncthreads();

        // ---- online softmax: warp w handles rows w*8 + (lane&7) ----
        {
            int row = w*8 + (lane & 7);
            int c0  = (lane >> 3) * 8;
            float* Sr = &sS[row*SSTR + c0];
            float sv[8];
            float mx = -FLT_MAX;
#pragma unroll
            for (int c = 0; c < 8; c++) { sv[c] = Sr[c]; mx = fmaxf(mx, sv[c]); }
            mx = fmaxf(mx, __shfl_xor_sync(0xffffffffu, mx, 8));
            mx = fmaxf(mx, __shfl_xor_sync(0xffffffffu, mx, 16));
            float mold = s_m[row];
            float mnew = fmaxf(mold, mx);
            float sum = 0.f;
            uint32_t phv[4], plv[4];
#pragma unroll
            for (int c = 0; c < 4; c++) {
                float p0 = __expf(sv[2*c]     - mnew);
                float p1 = __expf(sv[2*c + 1] - mnew);
                sum += p0 + p1;
                bf16 h0,h1,l0,l1; split2(p0,h0,l0); split2(p1,h1,l1);
                __nv_bfloat162 th, tl;
                th.x=h0; th.y=h1; tl.x=l0; tl.y=l1;
                phv[c] = *(uint32_t*)&th;
                plv[c] = *(uint32_t*)&tl;
            }
            sum += __shfl_xor_sync(0xffffffffu, sum, 8);
            sum += __shfl_xor_sync(0xffffffffu, sum, 16);
            if (lane < 8) {
                float f = __expf(mold - mnew);
                s_f[row] = f;
                s_m[row] = mnew;
                s_l[row] = s_l[row]*f + sum;
            }
#pragma unroll
            for (int c = 0; c < 4; c++) {
                *(uint32_t*)&sPh[row*VSTR + c0 + 2*c] = phv[c];
                *(uint32_t*)&sPl[row*VSTR + c0 + 2*c] = plv[c];
            }
        }
        __syncthreads();

        // ---- O = O*f + P @ V  (warp: 16 rows x 64 cols) ----
        {
            float fa = s_f[rbase + g];
            float fb = s_f[rbase + g + 8];
#pragma unroll
            for (int nt = 0; nt < 8; nt++) {
                O[nt][0] *= fa; O[nt][1] *= fa;
                O[nt][2] *= fb; O[nt][3] *= fb;
            }
#pragma unroll
            for (int ks = 0; ks < 2; ks++) {
                const int kb = ks * 16;
                uint32_t ah[4], al[4];
                ah[0] = *(uint32_t*)&sPh[(rbase+g  )*VSTR + kb + 2*p    ];
                ah[1] = *(uint32_t*)&sPh[(rbase+g+8)*VSTR + kb + 2*p    ];
                ah[2] = *(uint32_t*)&sPh[(rbase+g  )*VSTR + kb + 2*p + 8];
                ah[3] = *(uint32_t*)&sPh[(rbase+g+8)*VSTR + kb + 2*p + 8];
                al[0] = *(uint32_t*)&sPl[(rbase+g  )*VSTR + kb + 2*p    ];
                al[1] = *(uint32_t*)&sPl[(rbase+g+8)*VSTR + kb + 2*p    ];
                al[2] = *(uint32_t*)&sPl[(rbase+g  )*VSTR + kb + 2*p + 8];
                al[3] = *(uint32_t*)&sPl[(rbase+g+8)*VSTR + kb + 2*p + 8];
#pragma unroll
                for (int nt = 0; nt < 8; nt++) {
                    int nb = dnb + nt*8 + g;
                    uint32_t bh[2], bl[2];
                    bh[0] = *(uint32_t*)&sVh[nb*VSTR + kb + 2*p    ];
                    bh[1] = *(uint32_t*)&sVh[nb*VSTR + kb + 2*p + 8];
                    bl[0] = *(uint32_t*)&sVl[nb*VSTR + kb + 2*p    ];
                    bl[1] = *(uint32_t*)&sVl[nb*VSTR + kb + 2*p + 8];
                    mma16816(O[nt], ah, bh);
                    mma16816(O[nt], ah, bl);
                    mma16816(O[nt], al, bh);
                }
            }
        }
        __syncthreads();
    }

    // ---- finalize: O /= l, write ao split ----
    float ia = 1.f / s_l[rbase + g];
    float ib = 1.f / s_l[rbase + g + 8];
#pragma unroll
    for (int nt = 0; nt < 8; nt++)
#pragma unroll
    for (int half = 0; half < 2; half++) {
        int row = q0 + rbase + g + half*8;
        int col = h*HD + dnb + nt*8 + 2*p;
        float inv = half ? ib : ia;
        float v0 = O[nt][half*2]     * inv;
        float v1 = O[nt][half*2 + 1] * inv;
        size_t idx = (size_t)(b*NN + row)*DIMM + col;
        bf16 h0,h1,l0,l1; split2(v0,h0,l0); split2(v1,h1,l1);
        __nv_bfloat162 t;
        t.x=h0; t.y=h1; *(__nv_bfloat162*)&aoh[idx] = t;
        t.x=l0; t.y=l1; *(__nv_bfloat162*)&aol[idx] = t;
    }
}

// ---------------------------------------------------------------------------
extern "C" void kernel_launch(void* const* d_in, const int* in_sizes, int n_in,
                              void* d_out, int out_size)
{
    const float* x     = (const float*)d_in[0];
    const float* ctx   = (const float*)d_in[1];
    const float* dsim  = (const float*)d_in[2];
    const int*   mask  = (const int*)d_in[3];
    const int*   cmask = (const int*)d_in[4];
    const float* Wq    = (const float*)d_in[5];
    const float* Wkv   = (const float*)d_in[6];
    const float* beta  = (const float*)d_in[7];
    const float* Wout  = (const float*)d_in[8];
    const float* bout  = (const float*)d_in[9];
    float* out = (float*)d_out;

    bf16 *xh,*xl,*ch,*cl,*Wqh,*Wql,*Wkvh,*Wkvl,*Woh,*Wol;
    bf16 *qh,*ql,*kh,*kl,*vh,*vl,*aoh,*aol;
    cudaGetSymbolAddress((void**)&xh, g_xh);   cudaGetSymbolAddress((void**)&xl, g_xl);
    cudaGetSymbolAddress((void**)&ch, g_ch);   cudaGetSymbolAddress((void**)&cl, g_cl);
    cudaGetSymbolAddress((void**)&Wqh, g_Wqh); cudaGetSymbolAddress((void**)&Wql, g_Wql);
    cudaGetSymbolAddress((void**)&Wkvh, g_Wkvh); cudaGetSymbolAddress((void**)&Wkvl, g_Wkvl);
    cudaGetSymbolAddress((void**)&Woh, g_Woh); cudaGetSymbolAddress((void**)&Wol, g_Wol);
    cudaGetSymbolAddress((void**)&qh, g_qh);   cudaGetSymbolAddress((void**)&ql, g_ql);
    cudaGetSymbolAddress((void**)&kh, g_kh);   cudaGetSymbolAddress((void**)&kl, g_kl);
    cudaGetSymbolAddress((void**)&vh, g_vh);   cudaGetSymbolAddress((void**)&vl, g_vl);
    cudaGetSymbolAddress((void**)&aoh, g_aoh); cudaGetSymbolAddress((void**)&aol, g_aol);

    cudaFuncSetAttribute(attn_mma, cudaFuncAttributeMaxDynamicSharedMemorySize, ATTN_SMEM);

    // splits
    split_kernel<<<(2048*1024/4)/256, 256>>>(x,   xh,  xl,  2048*1024/4);
    split_kernel<<<(8192*1024/4)/256, 256>>>(ctx, ch,  cl,  8192*1024/4);
    split_kernel<<<(1024*1024/4)/256, 256>>>(Wq,  Wqh, Wql, 1024*1024/4);
    split_kernel<<<(2048*1024/4)/256, 256>>>(Wkv, Wkvh,Wkvl,2048*1024/4);
    split_kernel<<<(1024*1024/4)/256, 256>>>(Wout,Woh, Wol, 1024*1024/4);

    // q = x @ Wq^T  -> q split head-major
    gemm_split<1><<<dim3(1024/TN, 2048/TM), 256>>>(
        xh, xl, Wqh, Wql, 1024, nullptr, 0, nullptr, qh, ql, nullptr, nullptr);

    // kv = ctx @ Wkv^T -> k,v split head-major
    gemm_split<2><<<dim3(2048/TN, 8192/TM), 256>>>(
        ch, cl, Wkvh, Wkvl, 1024, nullptr, 0, nullptr, kh, kl, vh, vl);

    // attention
    attn_mma<<<dim3(NN/AQ, HH, BB), 256, ATTN_SMEM>>>(
        qh, ql, kh, kl, vh, vl, dsim, mask, cmask, beta, aoh, aol);

    // out = ao @ Wout^T + bout
    gemm_split<0><<<dim3(1024/TN, 2048/TM), 256>>>(
        aoh, aol, Woh, Wol, 1024, out, 1024, bout, nullptr, nullptr, nullptr, nullptr);
}

// round 5
// speedup vs baseline: 2.3407x; 1.4690x over previous
#include <cuda_runtime.h>
#include <cuda_bf16.h>
#include <cstdint>
#include <float.h>

typedef __nv_bfloat16 bf16;

// Problem constants
#define BB    2
#define NN    1024
#define MDOC  4
#define JJ    4096
#define DIMM  1024
#define HH    8
#define HD    128

// ---------------------------------------------------------------------------
// Device-global scratch (allocation-free rule)
// ---------------------------------------------------------------------------
__device__ bf16 g_xh[2048*1024],  g_xl[2048*1024];
__device__ bf16 g_ch[8192*1024],  g_cl[8192*1024];
__device__ bf16 g_Wqh[1024*1024], g_Wql[1024*1024];
__device__ bf16 g_Wkvh[2048*1024],g_Wkvl[2048*1024];
__device__ bf16 g_Woh[1024*1024], g_Wol[1024*1024];
__device__ bf16 g_qh[2048*1024],  g_ql[2048*1024];   // [b,h,n,d]
__device__ bf16 g_kh[8388608],    g_kl[8388608];     // [b,h,j,d]
__device__ bf16 g_vh[8388608],    g_vl[8388608];     // [b,h,j,d]
__device__ bf16 g_aoh[2048*1024], g_aol[2048*1024];  // [b*n, dim]

// ---------------------------------------------------------------------------
// PTX helpers
// ---------------------------------------------------------------------------
__device__ __forceinline__ void mma16816(float* c, const uint32_t* a, const uint32_t* b) {
    asm volatile(
        "mma.sync.aligned.m16n8k16.row.col.f32.bf16.bf16.f32 "
        "{%0,%1,%2,%3}, {%4,%5,%6,%7}, {%8,%9}, {%0,%1,%2,%3};\n"
        : "+f"(c[0]), "+f"(c[1]), "+f"(c[2]), "+f"(c[3])
        : "r"(a[0]), "r"(a[1]), "r"(a[2]), "r"(a[3]), "r"(b[0]), "r"(b[1]));
}

__device__ __forceinline__ uint32_t smu(const void* p) {
    return (uint32_t)__cvta_generic_to_shared(p);
}
__device__ __forceinline__ void cp16(uint32_t d, const void* s) {
    asm volatile("cp.async.cg.shared.global [%0], [%1], 16;\n" :: "r"(d), "l"(s));
}
__device__ __forceinline__ void cp_commit() {
    asm volatile("cp.async.commit_group;\n");
}
template<int N> __device__ __forceinline__ void cp_wait() {
    asm volatile("cp.async.wait_group %0;\n" :: "n"(N));
}
__device__ __forceinline__ void ldsm4(uint32_t* r, uint32_t a) {
    asm volatile("ldmatrix.sync.aligned.m8n8.x4.shared.b16 {%0,%1,%2,%3}, [%4];\n"
        : "=r"(r[0]), "=r"(r[1]), "=r"(r[2]), "=r"(r[3]) : "r"(a));
}
__device__ __forceinline__ void ldsm4t(uint32_t* r, uint32_t a) {
    asm volatile("ldmatrix.sync.aligned.m8n8.x4.trans.shared.b16 {%0,%1,%2,%3}, [%4];\n"
        : "=r"(r[0]), "=r"(r[1]), "=r"(r[2]), "=r"(r[3]) : "r"(a));
}

__device__ __forceinline__ void split2(float v, bf16& h, bf16& l) {
    h = __float2bfloat16(v);
    l = __float2bfloat16(v - __bfloat162float(h));
}

// ---------------------------------------------------------------------------
// fp32 -> (hi, lo) bf16 split conversion
// ---------------------------------------------------------------------------
__global__ void split_kernel(const float* __restrict__ in, bf16* __restrict__ hi,
                             bf16* __restrict__ lo, int n4)
{
    int i = blockIdx.x * blockDim.x + threadIdx.x;
    if (i >= n4) return;
    float4 v = ((const float4*)in)[i];
    bf16 h0,h1,h2,h3,l0,l1,l2,l3;
    split2(v.x,h0,l0); split2(v.y,h1,l1); split2(v.z,h2,l2); split2(v.w,h3,l3);
    __nv_bfloat162 a,b;
    a.x=h0; a.y=h1; b.x=h2; b.y=h3;
    *(__nv_bfloat162*)&hi[4*i]   = a;
    *(__nv_bfloat162*)&hi[4*i+2] = b;
    a.x=l0; a.y=l1; b.x=l2; b.y=l3;
    *(__nv_bfloat162*)&lo[4*i]   = a;
    *(__nv_bfloat162*)&lo[4*i+2] = b;
}

// ---------------------------------------------------------------------------
// Split-bf16 GEMM v2: C[M,N] = A[M,K] @ B[N,K]^T
// 128x64 tile, BK=32, 256 threads, warp tile 32x32.
// cp.async 2-stage pipeline + ldmatrix fragment loads.
// ---------------------------------------------------------------------------
#define TM 128
#define TN 64
#define TBK 32
#define PSTR 40          // smem row stride (bf16): 32 + 8 pad (80B, LDSM-clean)
#define GSTAGE (2*TM*PSTR + 2*TN*PSTR)         // bf16 elems per stage (15360)
#define GEMM_SMEM (2*GSTAGE*2)                 // bytes (61440)

template<int MODE>
__global__ __launch_bounds__(256, 2)
void gemm_split(const bf16* __restrict__ Ah, const bf16* __restrict__ Al,
                const bf16* __restrict__ Bh, const bf16* __restrict__ Bl,
                int K, float* __restrict__ C, int ldc,
                const float* __restrict__ bias,
                bf16* __restrict__ O1h, bf16* __restrict__ O1l,
                bf16* __restrict__ O2h, bf16* __restrict__ O2l)
{
    extern __shared__ bf16 smg[];

    const int tid  = threadIdx.x;
    const int lane = tid & 31, w = tid >> 5;
    const int g = lane >> 2, p = lane & 3;
    const int mwr = (w & 3) * 32;            // warp row base
    const int nwr = (w >> 2) * 32;           // warp col base
    const int m0 = blockIdx.y * TM, n0 = blockIdx.x * TN;

    float acc[2][4][4];
#pragma unroll
    for (int a = 0; a < 2; a++)
#pragma unroll
        for (int b = 0; b < 4; b++)
#pragma unroll
            for (int c = 0; c < 4; c++) acc[a][b][c] = 0.f;

    const int NT = K / TBK;

    // ---- stage loader ----
    auto load_stage = [&](int t, int s) {
        bf16* sAh = smg + s * GSTAGE;
        bf16* sAl = sAh + TM * PSTR;
        bf16* sBh = sAl + TM * PSTR;
        bf16* sBl = sBh + TN * PSTR;
        const int k0 = t * TBK;
#pragma unroll
        for (int i = 0; i < 2; i++) {
            int c = tid + i * 256;
            int r = c >> 2, c8 = (c & 3) * 8;
            cp16(smu(&sAh[r*PSTR + c8]), &Ah[(size_t)(m0+r)*K + k0 + c8]);
            cp16(smu(&sAl[r*PSTR + c8]), &Al[(size_t)(m0+r)*K + k0 + c8]);
        }
        {
            int r = tid >> 2, c8 = (tid & 3) * 8;
            cp16(smu(&sBh[r*PSTR + c8]), &Bh[(size_t)(n0+r)*K + k0 + c8]);
            cp16(smu(&sBl[r*PSTR + c8]), &Bl[(size_t)(n0+r)*K + k0 + c8]);
        }
        cp_commit();
    };

    load_stage(0, 0);

    for (int t = 0; t < NT; t++) {
        if (t + 1 < NT) { load_stage(t + 1, (t + 1) & 1); cp_wait<1>(); }
        else            { cp_wait<0>(); }
        __syncthreads();

        bf16* sAh = smg + (t & 1) * GSTAGE;
        bf16* sAl = sAh + TM * PSTR;
        bf16* sBh = sAl + TM * PSTR;
        bf16* sBl = sBh + TN * PSTR;

#pragma unroll
        for (int ks = 0; ks < 2; ks++) {
            const int kb = ks * 16;
            uint32_t ah[2][4], al[2][4];
#pragma unroll
            for (int mt = 0; mt < 2; mt++) {
                int aoff = (mwr + mt*16 + (lane & 15)) * PSTR + kb + (lane >> 4) * 8;
                ldsm4(ah[mt], smu(&sAh[aoff]));
                ldsm4(al[mt], smu(&sAl[aoff]));
            }
#pragma unroll
            for (int np = 0; np < 2; np++) {
                int boff = (nwr + np*16 + ((lane >> 4) << 3) + (lane & 7)) * PSTR
                         + kb + ((lane >> 3) & 1) * 8;
                uint32_t bh[4], bl[4];
                ldsm4(bh, smu(&sBh[boff]));
                ldsm4(bl, smu(&sBl[boff]));
#pragma unroll
                for (int h2 = 0; h2 < 2; h2++) {
#pragma unroll
                    for (int mt = 0; mt < 2; mt++) {
                        float* ac = acc[mt][np*2 + h2];
                        mma16816(ac, ah[mt], &bh[h2*2]);
                        mma16816(ac, ah[mt], &bl[h2*2]);
                        mma16816(ac, al[mt], &bh[h2*2]);
                    }
                }
            }
        }
        __syncthreads();
    }

    // ---- epilogue ----
#pragma unroll
    for (int mt = 0; mt < 2; mt++)
#pragma unroll
    for (int nt = 0; nt < 4; nt++)
#pragma unroll
    for (int half = 0; half < 2; half++) {
        int rm = m0 + mwr + mt*16 + g + half*8;
        int cg = n0 + nwr + nt*8 + 2*p;
        float v0 = acc[mt][nt][half*2];
        float v1 = acc[mt][nt][half*2 + 1];
        if (MODE == 0) {
            v0 += bias[cg]; v1 += bias[cg+1];
            float2 f2; f2.x = v0; f2.y = v1;
            *(float2*)&C[(size_t)rm*ldc + cg] = f2;
        } else if (MODE == 1) {
            int b = rm >> 10, n = rm & 1023;
            int hh = cg >> 7, d = cg & 127;
            size_t idx = (((size_t)(b*HH + hh))*NN + n)*HD + d;
            bf16 h0,h1,l0,l1; split2(v0,h0,l0); split2(v1,h1,l1);
            __nv_bfloat162 t2;
            t2.x=h0; t2.y=h1; *(__nv_bfloat162*)&O1h[idx] = t2;
            t2.x=l0; t2.y=l1; *(__nv_bfloat162*)&O1l[idx] = t2;
        } else {
            int b = rm >> 12, j = rm & 4095;
            int cc = cg;
            bf16 *dh, *dl;
            if (cc < 1024) { dh = O1h; dl = O1l; }
            else           { cc -= 1024; dh = O2h; dl = O2l; }
            int hh = cc >> 7, d = cc & 127;
            size_t idx = (((size_t)(b*HH + hh))*JJ + j)*HD + d;
            bf16 h0,h1,l0,l1; split2(v0,h0,l0); split2(v1,h1,l1);
            __nv_bfloat162 t2;
            t2.x=h0; t2.y=h1; *(__nv_bfloat162*)&dh[idx] = t2;
            t2.x=l0; t2.y=l1; *(__nv_bfloat162*)&dl[idx] = t2;
        }
    }
}

// ---------------------------------------------------------------------------
// Flash attention v2: BQ=64, BJ=32, 256 threads.
// cp.async double-buffered K/V stages; V row-major + ldmatrix.trans (no scalar
// transpose); ldmatrix for all fragments.
// ---------------------------------------------------------------------------
#define AQ 64
#define AJ 32
#define QST 136          // bf16 stride for Q/K/V rows (128 + 8 pad, 272B)
#define PST 40           // bf16 stride for P (80B)
#define SST 40           // fp32 stride for S

// smem layout (bf16 element offsets)
#define OFF_QH   0
#define OFF_QL   (AQ*QST)                 // 8704
#define OFF_STG  (2*AQ*QST)               // 17408
#define STG_SZ   (4*AJ*QST)               // 17408 per stage (Kh,Kl,Vh,Vl)
#define OFF_S_B  ((OFF_STG + 2*STG_SZ)*2) // byte offset of sS  = 104448
#define OFF_PH_B (OFF_S_B + AQ*SST*4)     // 114688
#define OFF_PL_B (OFF_PH_B + AQ*PST*2)    // 119808
#define OFF_MISC (OFF_PL_B + AQ*PST*2)    // 124928
#define ATTN_SMEM (OFF_MISC + 320*4 + 64) // ~126.3 KB

__global__ __launch_bounds__(256, 1)
void attn_mma(const bf16* __restrict__ qh, const bf16* __restrict__ ql,
              const bf16* __restrict__ kh, const bf16* __restrict__ kl,
              const bf16* __restrict__ vh, const bf16* __restrict__ vl,
              const float* __restrict__ ds, const int* __restrict__ mask,
              const int* __restrict__ cmask, const float* __restrict__ betap,
              bf16* __restrict__ aoh, bf16* __restrict__ aol)
{
    extern __shared__ char smc[];
    bf16*  sQh = (bf16*)smc;
    bf16*  sQl = sQh + OFF_QL;
    float* sS  = (float*)(smc + OFF_S_B);
    bf16*  sPh = (bf16*)(smc + OFF_PH_B);
    bf16*  sPl = (bf16*)(smc + OFF_PL_B);
    float* st  = (float*)(smc + OFF_MISC);
    float* s_rok = st;          // 64
    float* s_sim = st + 64;     // 32
    float* s_cok = st + 96;     // 32
    float* s_m   = st + 128;    // 64
    float* s_l   = st + 192;    // 64
    float* s_f   = st + 256;    // 64

    const int tid  = threadIdx.x;
    const int lane = tid & 31, w = tid >> 5;
    const int g = lane >> 2, p = lane & 3;
    const int b = blockIdx.z, h = blockIdx.y, q0 = blockIdx.x * AQ;
    const float beta  = *betap;
    const float scale = 0.03125f;

    const size_t qbase  = (((size_t)(b*HH + h))*NN + q0)*HD;
    const size_t kvbase = ((size_t)(b*HH + h))*JJ*HD;

    // ---- stage loader: Kh,Kl,Vh,Vl each 32x128 bf16 ----
    auto load_stage = [&](int jt, int s) {
        bf16* stg = sQh + OFF_STG + s * STG_SZ;
        bf16* dKh = stg;
        bf16* dKl = stg + AJ*QST;
        bf16* dVh = stg + 2*AJ*QST;
        bf16* dVl = stg + 3*AJ*QST;
        const size_t src0 = kvbase + (size_t)(jt * AJ) * HD;
#pragma unroll
        for (int i = 0; i < 2; i++) {
            int c = tid + i * 256;          // 0..511
            int r = c >> 4, c8 = (c & 15) * 8;
            size_t src = src0 + (size_t)r * HD + c8;
            int dst = r*QST + c8;
            cp16(smu(&dKh[dst]), &kh[src]);
            cp16(smu(&dKl[dst]), &kl[src]);
            cp16(smu(&dVh[dst]), &vh[src]);
            cp16(smu(&dVl[dst]), &vl[src]);
        }
        cp_commit();
    };

    // ---- load Q tile (plain, once) ----
#pragma unroll
    for (int i = 0; i < 4; i++) {
        int li = tid + i * 256;
        int r = li >> 4, cc = (li & 15) * 8;
        *(uint4*)&sQh[r*QST + cc] = *(const uint4*)&qh[qbase + (size_t)r*HD + cc];
        *(uint4*)&sQl[r*QST + cc] = *(const uint4*)&ql[qbase + (size_t)r*HD + cc];
    }
    if (tid < AQ) {
        s_rok[tid] = (mask[b*NN + q0 + tid] != 0) ? 1.f : 0.f;
        s_m[tid] = -FLT_MAX;
        s_l[tid] = 0.f;
    }

    load_stage(0, 0);

    const int rbase = (w & 3) * 16;   // warp row base
    const int snb   = (w >> 2) * 16;  // S col base
    const int dnb   = (w >> 2) * 64;  // PV col base

    float O[8][4];
#pragma unroll
    for (int a = 0; a < 8; a++)
#pragma unroll
        for (int c = 0; c < 4; c++) O[a][c] = 0.f;

    const int NTILE = JJ / AJ;
    for (int jt = 0; jt < NTILE; jt++) {
        if (jt + 1 < NTILE) { load_stage(jt + 1, (jt + 1) & 1); cp_wait<1>(); }
        else                { cp_wait<0>(); }
        if (tid < AJ) {
            int jc = jt * AJ + tid;
            s_sim[tid] = ds[b*MDOC + (jc >> 10)] * beta;
            s_cok[tid] = (cmask[b*JJ + jc] != 0) ? 1.f : 0.f;
        }
        __syncthreads();

        bf16* stg = sQh + OFF_STG + (jt & 1) * STG_SZ;
        bf16* sKh = stg;
        bf16* sKl = stg + AJ*QST;
        bf16* sVh = stg + 2*AJ*QST;
        bf16* sVl = stg + 3*AJ*QST;

        // ---- S = Q @ K^T ----
        float SA[2][4];
#pragma unroll
        for (int nt = 0; nt < 2; nt++)
#pragma unroll
            for (int c = 0; c < 4; c++) SA[nt][c] = 0.f;
#pragma unroll
        for (int ks = 0; ks < 8; ks++) {
            const int kb = ks * 16;
            uint32_t ah[4], al[4], bh[4], bl[4];
            int aoff = (rbase + (lane & 15)) * QST + kb + (lane >> 4) * 8;
            ldsm4(ah, smu(&sQh[aoff]));
            ldsm4(al, smu(&sQl[aoff]));
            int boff = (snb + ((lane >> 4) << 3) + (lane & 7)) * QST
                     + kb + ((lane >> 3) & 1) * 8;
            ldsm4(bh, smu(&sKh[boff]));
            ldsm4(bl, smu(&sKl[boff]));
#pragma unroll
            for (int h2 = 0; h2 < 2; h2++) {
                mma16816(SA[h2], ah, &bh[h2*2]);
                mma16816(SA[h2], ah, &bl[h2*2]);
                mma16816(SA[h2], al, &bh[h2*2]);
            }
        }
        // store S with scale + bias + mask
#pragma unroll
        for (int nt = 0; nt < 2; nt++)
#pragma unroll
        for (int half = 0; half < 2; half++) {
            int row = rbase + g + half*8;
            int col = snb + nt*8 + 2*p;
            float okr = s_rok[row];
            float v0 = SA[nt][half*2]     * scale + s_sim[col];
            float v1 = SA[nt][half*2 + 1] * scale + s_sim[col+1];
            bool ok0 = (okr > 0.5f) && (s_cok[col]   > 0.5f);
            bool ok1 = (okr > 0.5f) && (s_cok[col+1] > 0.5f);
            sS[row*SST + col]     = ok0 ? v0 : -FLT_MAX;
            sS[row*SST + col + 1] = ok1 ? v1 : -FLT_MAX;
        }
        __syncthreads();

        // ---- online softmax ----
        {
            int row = w*8 + (lane & 7);
            int c0  = (lane >> 3) * 8;
            float* Sr = &sS[row*SST + c0];
            float sv[8];
            float mx = -FLT_MAX;
#pragma unroll
            for (int c = 0; c < 8; c++) { sv[c] = Sr[c]; mx = fmaxf(mx, sv[c]); }
            mx = fmaxf(mx, __shfl_xor_sync(0xffffffffu, mx, 8));
            mx = fmaxf(mx, __shfl_xor_sync(0xffffffffu, mx, 16));
            float mold = s_m[row];
            float mnew = fmaxf(mold, mx);
            float sum = 0.f;
            uint32_t phv[4], plv[4];
#pragma unroll
            for (int c = 0; c < 4; c++) {
                float p0 = __expf(sv[2*c]     - mnew);
                float p1 = __expf(sv[2*c + 1] - mnew);
                sum += p0 + p1;
                bf16 h0,h1,l0,l1; split2(p0,h0,l0); split2(p1,h1,l1);
                __nv_bfloat162 th, tl;
                th.x=h0; th.y=h1; tl.x=l0; tl.y=l1;
                phv[c] = *(uint32_t*)&th;
                plv[c] = *(uint32_t*)&tl;
            }
            sum += __shfl_xor_sync(0xffffffffu, sum, 8);
            sum += __shfl_xor_sync(0xffffffffu, sum, 16);
            if (lane < 8) {
                float f = __expf(mold - mnew);
                s_f[row] = f;
                s_m[row] = mnew;
                s_l[row] = s_l[row]*f + sum;
            }
#pragma unroll
            for (int c = 0; c < 4; c++) {
                *(uint32_t*)&sPh[row*PST + c0 + 2*c] = phv[c];
                *(uint32_t*)&sPl[row*PST + c0 + 2*c] = plv[c];
            }
        }
        __syncthreads();

        // ---- O = O*f + P @ V ----
        {
            float fa = s_f[rbase + g];
            float fb = s_f[rbase + g + 8];
#pragma unroll
            for (int nt = 0; nt < 8; nt++) {
                O[nt][0] *= fa; O[nt][1] *= fa;
                O[nt][2] *= fb; O[nt][3] *= fb;
            }
#pragma unroll
            for (int ks = 0; ks < 2; ks++) {
                const int kb = ks * 16;
                uint32_t ah[4], al[4];
                int aoff = (rbase + (lane & 15)) * PST + kb + (lane >> 4) * 8;
                ldsm4(ah, smu(&sPh[aoff]));
                ldsm4(al, smu(&sPl[aoff]));
#pragma unroll
                for (int dp = 0; dp < 4; dp++) {
                    int nb = dnb + dp*16;
                    int boff = (kb + ((lane >> 3) & 1) * 8 + (lane & 7)) * QST
                             + nb + (lane >> 4) * 8;
                    uint32_t bh[4], bl[4];
                    ldsm4t(bh, smu(&sVh[boff]));
                    ldsm4t(bl, smu(&sVl[boff]));
#pragma unroll
                    for (int h2 = 0; h2 < 2; h2++) {
                        float* ac = O[dp*2 + h2];
                        mma16816(ac, ah, &bh[h2*2]);
                        mma16816(ac, ah, &bl[h2*2]);
                        mma16816(ac, al, &bh[h2*2]);
                    }
                }
            }
        }
        __syncthreads();
    }

    // ---- finalize ----
    float ia = 1.f / s_l[rbase + g];
    float ib = 1.f / s_l[rbase + g + 8];
#pragma unroll
    for (int nt = 0; nt < 8; nt++)
#pragma unroll
    for (int half = 0; half < 2; half++) {
        int row = q0 + rbase + g + half*8;
        int col = h*HD + dnb + nt*8 + 2*p;
        float inv = half ? ib : ia;
        float v0 = O[nt][half*2]     * inv;
        float v1 = O[nt][half*2 + 1] * inv;
        size_t idx = (size_t)(b*NN + row)*DIMM + col;
        bf16 h0,h1,l0,l1; split2(v0,h0,l0); split2(v1,h1,l1);
        __nv_bfloat162 t2;
        t2.x=h0; t2.y=h1; *(__nv_bfloat162*)&aoh[idx] = t2;
        t2.x=l0; t2.y=l1; *(__nv_bfloat162*)&aol[idx] = t2;
    }
}

// ---------------------------------------------------------------------------
extern "C" void kernel_launch(void* const* d_in, const int* in_sizes, int n_in,
                              void* d_out, int out_size)
{
    const float* x     = (const float*)d_in[0];
    const float* ctx   = (const float*)d_in[1];
    const float* dsim  = (const float*)d_in[2];
    const int*   mask  = (const int*)d_in[3];
    const int*   cmask = (const int*)d_in[4];
    const float* Wq    = (const float*)d_in[5];
    const float* Wkv   = (const float*)d_in[6];
    const float* beta  = (const float*)d_in[7];
    const float* Wout  = (const float*)d_in[8];
    const float* bout  = (const float*)d_in[9];
    float* out = (float*)d_out;

    bf16 *xh,*xl,*ch,*cl,*Wqh,*Wql,*Wkvh,*Wkvl,*Woh,*Wol;
    bf16 *qh,*ql,*kh,*kl,*vh,*vl,*aoh,*aol;
    cudaGetSymbolAddress((void**)&xh, g_xh);   cudaGetSymbolAddress((void**)&xl, g_xl);
    cudaGetSymbolAddress((void**)&ch, g_ch);   cudaGetSymbolAddress((void**)&cl, g_cl);
    cudaGetSymbolAddress((void**)&Wqh, g_Wqh); cudaGetSymbolAddress((void**)&Wql, g_Wql);
    cudaGetSymbolAddress((void**)&Wkvh, g_Wkvh); cudaGetSymbolAddress((void**)&Wkvl, g_Wkvl);
    cudaGetSymbolAddress((void**)&Woh, g_Woh); cudaGetSymbolAddress((void**)&Wol, g_Wol);
    cudaGetSymbolAddress((void**)&qh, g_qh);   cudaGetSymbolAddress((void**)&ql, g_ql);
    cudaGetSymbolAddress((void**)&kh, g_kh);   cudaGetSymbolAddress((void**)&kl, g_kl);
    cudaGetSymbolAddress((void**)&vh, g_vh);   cudaGetSymbolAddress((void**)&vl, g_vl);
    cudaGetSymbolAddress((void**)&aoh, g_aoh); cudaGetSymbolAddress((void**)&aol, g_aol);

    cudaFuncSetAttribute(gemm_split<0>, cudaFuncAttributeMaxDynamicSharedMemorySize, GEMM_SMEM);
    cudaFuncSetAttribute(gemm_split<1>, cudaFuncAttributeMaxDynamicSharedMemorySize, GEMM_SMEM);
    cudaFuncSetAttribute(gemm_split<2>, cudaFuncAttributeMaxDynamicSharedMemorySize, GEMM_SMEM);
    cudaFuncSetAttribute(attn_mma, cudaFuncAttributeMaxDynamicSharedMemorySize, ATTN_SMEM);

    // splits
    split_kernel<<<(2048*1024/4)/256, 256>>>(x,   xh,  xl,  2048*1024/4);
    split_kernel<<<(8192*1024/4)/256, 256>>>(ctx, ch,  cl,  8192*1024/4);
    split_kernel<<<(1024*1024/4)/256, 256>>>(Wq,  Wqh, Wql, 1024*1024/4);
    split_kernel<<<(2048*1024/4)/256, 256>>>(Wkv, Wkvh,Wkvl,2048*1024/4);
    split_kernel<<<(1024*1024/4)/256, 256>>>(Wout,Woh, Wol, 1024*1024/4);

    // q = x @ Wq^T  -> q split head-major
    gemm_split<1><<<dim3(1024/TN, 2048/TM), 256, GEMM_SMEM>>>(
        xh, xl, Wqh, Wql, 1024, nullptr, 0, nullptr, qh, ql, nullptr, nullptr);

    // kv = ctx @ Wkv^T -> k,v split head-major
    gemm_split<2><<<dim3(2048/TN, 8192/TM), 256, GEMM_SMEM>>>(
        ch, cl, Wkvh, Wkvl, 1024, nullptr, 0, nullptr, kh, kl, vh, vl);

    // attention
    attn_mma<<<dim3(NN/AQ, HH, BB), 256, ATTN_SMEM>>>(
        qh, ql, kh, kl, vh, vl, dsim, mask, cmask, beta, aoh, aol);

    // out = ao @ Wout^T + bout
    gemm_split<0><<<dim3(1024/TN, 2048/TM), 256, GEMM_SMEM>>>(
        aoh, aol, Woh, Wol, 1024, out, 1024, bout, nullptr, nullptr, nullptr, nullptr);
}

// round 8
// speedup vs baseline: 3.2835x; 1.4028x over previous
#include <cuda_runtime.h>
#include <cuda_bf16.h>
#include <cstdint>
#include <float.h>

typedef __nv_bfloat16 bf16;

// Problem constants
#define BB    2
#define NN    1024
#define MDOC  4
#define JJ    4096
#define DIMM  1024
#define HH    8
#define HD    128

// ---------------------------------------------------------------------------
// Device-global scratch (allocation-free rule)
// ---------------------------------------------------------------------------
__device__ bf16 g_xh[2048*1024],  g_xl[2048*1024];
__device__ bf16 g_ch[8192*1024],  g_cl[8192*1024];
__device__ bf16 g_Wqh[1024*1024], g_Wql[1024*1024];
__device__ bf16 g_Wkvh[2048*1024],g_Wkvl[2048*1024];
__device__ bf16 g_Woh[1024*1024], g_Wol[1024*1024];
__device__ bf16 g_qh[2048*1024],  g_ql[2048*1024];   // [b,h,n,d]
__device__ bf16 g_kh[8388608],    g_kl[8388608];     // [b,h,j,d]
__device__ bf16 g_vh[8388608],    g_vl[8388608];     // [b,h,j,d]
__device__ bf16 g_aoh[2048*1024], g_aol[2048*1024];  // [b*n, dim]

// ---------------------------------------------------------------------------
// PTX helpers
// ---------------------------------------------------------------------------
__device__ __forceinline__ void mma16816(float* c, const uint32_t* a, const uint32_t* b) {
    asm volatile(
        "mma.sync.aligned.m16n8k16.row.col.f32.bf16.bf16.f32 "
        "{%0,%1,%2,%3}, {%4,%5,%6,%7}, {%8,%9}, {%0,%1,%2,%3};\n"
        : "+f"(c[0]), "+f"(c[1]), "+f"(c[2]), "+f"(c[3])
        : "r"(a[0]), "r"(a[1]), "r"(a[2]), "r"(a[3]), "r"(b[0]), "r"(b[1]));
}

__device__ __forceinline__ uint32_t smu(const void* p) {
    return (uint32_t)__cvta_generic_to_shared(p);
}
__device__ __forceinline__ void cp16(uint32_t d, const void* s) {
    asm volatile("cp.async.cg.shared.global [%0], [%1], 16;\n" :: "r"(d), "l"(s));
}
__device__ __forceinline__ void cp_commit() {
    asm volatile("cp.async.commit_group;\n");
}
template<int N> __device__ __forceinline__ void cp_wait() {
    asm volatile("cp.async.wait_group %0;\n" :: "n"(N));
}
__device__ __forceinline__ void ldsm4(uint32_t* r, uint32_t a) {
    asm volatile("ldmatrix.sync.aligned.m8n8.x4.shared.b16 {%0,%1,%2,%3}, [%4];\n"
        : "=r"(r[0]), "=r"(r[1]), "=r"(r[2]), "=r"(r[3]) : "r"(a));
}
__device__ __forceinline__ void ldsm4t(uint32_t* r, uint32_t a) {
    asm volatile("ldmatrix.sync.aligned.m8n8.x4.trans.shared.b16 {%0,%1,%2,%3}, [%4];\n"
        : "=r"(r[0]), "=r"(r[1]), "=r"(r[2]), "=r"(r[3]) : "r"(a));
}

__device__ __forceinline__ void split2(float v, bf16& h, bf16& l) {
    h = __float2bfloat16(v);
    l = __float2bfloat16(v - __bfloat162float(h));
}
__device__ __forceinline__ void pack2(float a, float b, uint32_t& hi, uint32_t& lo) {
    bf16 ha,la,hb,lb; split2(a,ha,la); split2(b,hb,lb);
    __nv_bfloat162 th, tl;
    th.x=ha; th.y=hb; tl.x=la; tl.y=lb;
    hi = *(uint32_t*)&th; lo = *(uint32_t*)&tl;
}

// ---------------------------------------------------------------------------
// fp32 -> (hi, lo) bf16 split conversion
// ---------------------------------------------------------------------------
__global__ void split_kernel(const float* __restrict__ in, bf16* __restrict__ hi,
                             bf16* __restrict__ lo, int n4)
{
    int i = blockIdx.x * blockDim.x + threadIdx.x;
    if (i >= n4) return;
    float4 v = ((const float4*)in)[i];
    bf16 h0,h1,h2,h3,l0,l1,l2,l3;
    split2(v.x,h0,l0); split2(v.y,h1,l1); split2(v.z,h2,l2); split2(v.w,h3,l3);
    __nv_bfloat162 a,b;
    a.x=h0; a.y=h1; b.x=h2; b.y=h3;
    *(__nv_bfloat162*)&hi[4*i]   = a;
    *(__nv_bfloat162*)&hi[4*i+2] = b;
    a.x=l0; a.y=l1; b.x=l2; b.y=l3;
    *(__nv_bfloat162*)&lo[4*i]   = a;
    *(__nv_bfloat162*)&lo[4*i+2] = b;
}

// ---------------------------------------------------------------------------
// Split-bf16 GEMM: C[M,N] = A[M,K] @ B[N,K]^T  (unchanged from round 5)
// ---------------------------------------------------------------------------
#define TM 128
#define TN 64
#define TBK 32
#define PSTR 40
#define GSTAGE (2*TM*PSTR + 2*TN*PSTR)
#define GEMM_SMEM (2*GSTAGE*2)

template<int MODE>
__global__ __launch_bounds__(256, 2)
void gemm_split(const bf16* __restrict__ Ah, const bf16* __restrict__ Al,
                const bf16* __restrict__ Bh, const bf16* __restrict__ Bl,
                int K, float* __restrict__ C, int ldc,
                const float* __restrict__ bias,
                bf16* __restrict__ O1h, bf16* __restrict__ O1l,
                bf16* __restrict__ O2h, bf16* __restrict__ O2l)
{
    extern __shared__ bf16 smg[];

    const int tid  = threadIdx.x;
    const int lane = tid & 31, w = tid >> 5;
    const int g = lane >> 2, p = lane & 3;
    const int mwr = (w & 3) * 32;
    const int nwr = (w >> 2) * 32;
    const int m0 = blockIdx.y * TM, n0 = blockIdx.x * TN;

    float acc[2][4][4];
#pragma unroll
    for (int a = 0; a < 2; a++)
#pragma unroll
        for (int b = 0; b < 4; b++)
#pragma unroll
            for (int c = 0; c < 4; c++) acc[a][b][c] = 0.f;

    const int NT = K / TBK;

    auto load_stage = [&](int t, int s) {
        bf16* sAh = smg + s * GSTAGE;
        bf16* sAl = sAh + TM * PSTR;
        bf16* sBh = sAl + TM * PSTR;
        bf16* sBl = sBh + TN * PSTR;
        const int k0 = t * TBK;
#pragma unroll
        for (int i = 0; i < 2; i++) {
            int c = tid + i * 256;
            int r = c >> 2, c8 = (c & 3) * 8;
            cp16(smu(&sAh[r*PSTR + c8]), &Ah[(size_t)(m0+r)*K + k0 + c8]);
            cp16(smu(&sAl[r*PSTR + c8]), &Al[(size_t)(m0+r)*K + k0 + c8]);
        }
        {
            int r = tid >> 2, c8 = (tid & 3) * 8;
            cp16(smu(&sBh[r*PSTR + c8]), &Bh[(size_t)(n0+r)*K + k0 + c8]);
            cp16(smu(&sBl[r*PSTR + c8]), &Bl[(size_t)(n0+r)*K + k0 + c8]);
        }
        cp_commit();
    };

    load_stage(0, 0);

    for (int t = 0; t < NT; t++) {
        if (t + 1 < NT) { load_stage(t + 1, (t + 1) & 1); cp_wait<1>(); }
        else            { cp_wait<0>(); }
        __syncthreads();

        bf16* sAh = smg + (t & 1) * GSTAGE;
        bf16* sAl = sAh + TM * PSTR;
        bf16* sBh = sAl + TM * PSTR;
        bf16* sBl = sBh + TN * PSTR;

#pragma unroll
        for (int ks = 0; ks < 2; ks++) {
            const int kb = ks * 16;
            uint32_t ah[2][4], al[2][4];
#pragma unroll
            for (int mt = 0; mt < 2; mt++) {
                int aoff = (mwr + mt*16 + (lane & 15)) * PSTR + kb + (lane >> 4) * 8;
                ldsm4(ah[mt], smu(&sAh[aoff]));
                ldsm4(al[mt], smu(&sAl[aoff]));
            }
#pragma unroll
            for (int np = 0; np < 2; np++) {
                int boff = (nwr + np*16 + ((lane >> 4) << 3) + (lane & 7)) * PSTR
                         + kb + ((lane >> 3) & 1) * 8;
                uint32_t bh[4], bl[4];
                ldsm4(bh, smu(&sBh[boff]));
                ldsm4(bl, smu(&sBl[boff]));
#pragma unroll
                for (int h2 = 0; h2 < 2; h2++) {
#pragma unroll
                    for (int mt = 0; mt < 2; mt++) {
                        float* ac = acc[mt][np*2 + h2];
                        mma16816(ac, ah[mt], &bh[h2*2]);
                        mma16816(ac, ah[mt], &bl[h2*2]);
                        mma16816(ac, al[mt], &bh[h2*2]);
                    }
                }
            }
        }
        __syncthreads();
    }

#pragma unroll
    for (int mt = 0; mt < 2; mt++)
#pragma unroll
    for (int nt = 0; nt < 4; nt++)
#pragma unroll
    for (int half = 0; half < 2; half++) {
        int rm = m0 + mwr + mt*16 + g + half*8;
        int cg = n0 + nwr + nt*8 + 2*p;
        float v0 = acc[mt][nt][half*2];
        float v1 = acc[mt][nt][half*2 + 1];
        if (MODE == 0) {
            v0 += bias[cg]; v1 += bias[cg+1];
            float2 f2; f2.x = v0; f2.y = v1;
            *(float2*)&C[(size_t)rm*ldc + cg] = f2;
        } else if (MODE == 1) {
            int b = rm >> 10, n = rm & 1023;
            int hh = cg >> 7, d = cg & 127;
            size_t idx = (((size_t)(b*HH + hh))*NN + n)*HD + d;
            uint32_t hi, lo; pack2(v0, v1, hi, lo);
            *(uint32_t*)&O1h[idx] = hi;
            *(uint32_t*)&O1l[idx] = lo;
        } else {
            int b = rm >> 12, j = rm & 4095;
            int cc = cg;
            bf16 *dh, *dl;
            if (cc < 1024) { dh = O1h; dl = O1l; }
            else           { cc -= 1024; dh = O2h; dl = O2l; }
            int hh = cc >> 7, d = cc & 127;
            size_t idx = (((size_t)(b*HH + hh))*JJ + j)*HD + d;
            uint32_t hi, lo; pack2(v0, v1, hi, lo);
            *(uint32_t*)&dh[idx] = hi;
            *(uint32_t*)&dl[idx] = lo;
        }
    }
}

// ---------------------------------------------------------------------------
// Flash attention v3 (FA2-style): BQ=64, BJ=32, 128 threads, 2 CTAs/SM.
// 4 warps, each owns 16 q-rows x all 32 j-cols. S stays in registers; the
// QK C-fragment layout IS the PV A-fragment layout -> no S/P smem roundtrip.
// Q fragments hoisted to registers. cp.async double-buffered K/V stages.
// ---------------------------------------------------------------------------
#define AQ 64
#define AJ 32
#define QST 136                              // bf16 row stride (272 B)
#define OFFB_QL   (AQ*QST*2)                 // 17408
#define OFFB_STG  (2*AQ*QST*2)               // 34816
#define STGB      (4*AJ*QST*2)               // 34816 per stage (Kh,Kl,Vh,Vl)
#define OFFB_MISC (OFFB_STG + 2*STGB)        // 104448
#define ATTN_SMEM (OFFB_MISC + 96*4)         // 104832 B

__global__ __launch_bounds__(128, 2)
void attn_mma(const bf16* __restrict__ qh, const bf16* __restrict__ ql,
              const bf16* __restrict__ kh, const bf16* __restrict__ kl,
              const bf16* __restrict__ vh, const bf16* __restrict__ vl,
              const float* __restrict__ ds, const int* __restrict__ mask,
              const int* __restrict__ cmask, const float* __restrict__ betap,
              bf16* __restrict__ aoh, bf16* __restrict__ aol)
{
    extern __shared__ char smc[];
    bf16* sQh = (bf16*)smc;
    bf16* sQl = (bf16*)(smc + OFFB_QL);
    float* s_rok = (float*)(smc + OFFB_MISC);   // [64]
    float* s_cok = s_rok + 64;                  // [32]

    const int tid  = threadIdx.x;
    const int lane = tid & 31, w = tid >> 5;    // 4 warps
    const int g = lane >> 2, p = lane & 3;
    const int b = blockIdx.z, h = blockIdx.y, q0 = blockIdx.x * AQ;
    const float beta  = *betap;
    const float scale = 0.03125f;
    const int rbase = w * 16;

    const size_t qbase  = (((size_t)(b*HH + h))*NN + q0)*HD;
    const size_t kvbase = ((size_t)(b*HH + h))*JJ*HD;

    float sim_arr[4];
#pragma unroll
    for (int i = 0; i < 4; i++) sim_arr[i] = ds[b*MDOC + i] * beta;

    // ---- load Q tile (once) ----
#pragma unroll
    for (int i = 0; i < 8; i++) {
        int li = tid + i * 128;
        int r = li >> 4, c8 = (li & 15) * 8;
        *(uint4*)&sQh[r*QST + c8] = *(const uint4*)&qh[qbase + (size_t)r*HD + c8];
        *(uint4*)&sQl[r*QST + c8] = *(const uint4*)&ql[qbase + (size_t)r*HD + c8];
    }
    if (tid < 64) s_rok[tid] = (mask[b*NN + q0 + tid] != 0) ? 1.f : 0.f;

    // ---- stage loader ----
    auto load_stage = [&](int jt, int s) {
        bf16* stg = (bf16*)(smc + OFFB_STG + s * STGB);
        bf16* dKh = stg;
        bf16* dKl = stg + AJ*QST;
        bf16* dVh = stg + 2*AJ*QST;
        bf16* dVl = stg + 3*AJ*QST;
        const size_t src0 = kvbase + (size_t)(jt * AJ) * HD;
#pragma unroll
        for (int i = 0; i < 4; i++) {
            int c = tid + i * 128;            // 0..511
            int r = c >> 4, c8 = (c & 15) * 8;
            size_t src = src0 + (size_t)r * HD + c8;
            int dst = r*QST + c8;
            cp16(smu(&dKh[dst]), &kh[src]);
            cp16(smu(&dKl[dst]), &kl[src]);
            cp16(smu(&dVh[dst]), &vh[src]);
            cp16(smu(&dVl[dst]), &vl[src]);
        }
        cp_commit();
    };

    load_stage(0, 0);
    __syncthreads();

    // ---- hoist Q fragments to registers ----
    uint32_t qfh[8][4], qfl[8][4];
#pragma unroll
    for (int ks = 0; ks < 8; ks++) {
        int aoff = (rbase + (lane & 15)) * QST + ks*16 + (lane >> 4) * 8;
        ldsm4(qfh[ks], smu(&sQh[aoff]));
        ldsm4(qfl[ks], smu(&sQl[aoff]));
    }

    const float rok0 = s_rok[rbase + g];
    const float rok1 = s_rok[rbase + g + 8];
    float m0 = -FLT_MAX, m1 = -FLT_MAX, l0 = 0.f, l1 = 0.f;

    float O[16][4];
#pragma unroll
    for (int a = 0; a < 16; a++)
#pragma unroll
        for (int c = 0; c < 4; c++) O[a][c] = 0.f;

    const int NTILE = JJ / AJ;    // 128
    for (int jt = 0; jt < NTILE; jt++) {
        if (jt + 1 < NTILE) { load_stage(jt + 1, (jt + 1) & 1); cp_wait<1>(); }
        else                { cp_wait<0>(); }
        if (tid < AJ)
            s_cok[tid] = (cmask[b*JJ + jt*AJ + tid] != 0) ? 1.f : 0.f;
        __syncthreads();

        bf16* stg = (bf16*)(smc + OFFB_STG + (jt & 1) * STGB);
        bf16* sKh = stg;
        bf16* sKl = stg + AJ*QST;
        bf16* sVh = stg + 2*AJ*QST;
        bf16* sVl = stg + 3*AJ*QST;

        // ---- S = Q @ K^T  (warp: 16 rows x 32 cols, registers) ----
        float SA[4][4];
#pragma unroll
        for (int nf = 0; nf < 4; nf++)
#pragma unroll
            for (int c = 0; c < 4; c++) SA[nf][c] = 0.f;
#pragma unroll
        for (int ks = 0; ks < 8; ks++) {
            const int kb = ks * 16;
            uint32_t bh0[4], bl0[4], bh1[4], bl1[4];
            int b0 = (((lane >> 4) << 3) + (lane & 7)) * QST + kb + ((lane >> 3) & 1) * 8;
            int b1 = b0 + 16 * QST;
            ldsm4(bh0, smu(&sKh[b0]));
            ldsm4(bl0, smu(&sKl[b0]));
            ldsm4(bh1, smu(&sKh[b1]));
            ldsm4(bl1, smu(&sKl[b1]));
            mma16816(SA[0], qfh[ks], &bh0[0]);
            mma16816(SA[0], qfh[ks], &bl0[0]);
            mma16816(SA[0], qfl[ks], &bh0[0]);
            mma16816(SA[1], qfh[ks], &bh0[2]);
            mma16816(SA[1], qfh[ks], &bl0[2]);
            mma16816(SA[1], qfl[ks], &bh0[2]);
            mma16816(SA[2], qfh[ks], &bh1[0]);
            mma16816(SA[2], qfh[ks], &bl1[0]);
            mma16816(SA[2], qfl[ks], &bh1[0]);
            mma16816(SA[3], qfh[ks], &bh1[2]);
            mma16816(SA[3], qfh[ks], &bl1[2]);
            mma16816(SA[3], qfl[ks], &bh1[2]);
        }

        // ---- mask + scale + bias, online softmax (all registers) ----
        const float simt = sim_arr[jt >> 5];
        float sv0[8], sv1[8];
#pragma unroll
        for (int nf = 0; nf < 4; nf++) {
            float ck0 = s_cok[nf*8 + 2*p];
            float ck1 = s_cok[nf*8 + 2*p + 1];
            sv0[2*nf]   = (rok0 > 0.5f && ck0 > 0.5f) ? SA[nf][0]*scale + simt : -FLT_MAX;
            sv0[2*nf+1] = (rok0 > 0.5f && ck1 > 0.5f) ? SA[nf][1]*scale + simt : -FLT_MAX;
            sv1[2*nf]   = (rok1 > 0.5f && ck0 > 0.5f) ? SA[nf][2]*scale + simt : -FLT_MAX;
            sv1[2*nf+1] = (rok1 > 0.5f && ck1 > 0.5f) ? SA[nf][3]*scale + simt : -FLT_MAX;
        }
        float mx0 = -FLT_MAX, mx1 = -FLT_MAX;
#pragma unroll
        for (int c = 0; c < 8; c++) { mx0 = fmaxf(mx0, sv0[c]); mx1 = fmaxf(mx1, sv1[c]); }
        mx0 = fmaxf(mx0, __shfl_xor_sync(0xffffffffu, mx0, 1));
        mx0 = fmaxf(mx0, __shfl_xor_sync(0xffffffffu, mx0, 2));
        mx1 = fmaxf(mx1, __shfl_xor_sync(0xffffffffu, mx1, 1));
        mx1 = fmaxf(mx1, __shfl_xor_sync(0xffffffffu, mx1, 2));
        float mn0 = fmaxf(m0, mx0), mn1 = fmaxf(m1, mx1);
        float f0 = __expf(m0 - mn0), f1 = __expf(m1 - mn1);
        m0 = mn0; m1 = mn1;
        float pv0[8], pv1[8], sm0 = 0.f, sm1 = 0.f;
#pragma unroll
        for (int c = 0; c < 8; c++) {
            pv0[c] = __expf(sv0[c] - mn0); sm0 += pv0[c];
            pv1[c] = __expf(sv1[c] - mn1); sm1 += pv1[c];
        }
        sm0 += __shfl_xor_sync(0xffffffffu, sm0, 1);
        sm0 += __shfl_xor_sync(0xffffffffu, sm0, 2);
        sm1 += __shfl_xor_sync(0xffffffffu, sm1, 1);
        sm1 += __shfl_xor_sync(0xffffffffu, sm1, 2);
        l0 = l0*f0 + sm0;
        l1 = l1*f1 + sm1;

        // ---- pack P directly into PV A-fragments ----
        uint32_t pah[2][4], pal[2][4];
#pragma unroll
        for (int kf = 0; kf < 2; kf++) {
            int bs = kf * 4;
            pack2(pv0[bs+0], pv0[bs+1], pah[kf][0], pal[kf][0]);
            pack2(pv1[bs+0], pv1[bs+1], pah[kf][1], pal[kf][1]);
            pack2(pv0[bs+2], pv0[bs+3], pah[kf][2], pal[kf][2]);
            pack2(pv1[bs+2], pv1[bs+3], pah[kf][3], pal[kf][3]);
        }

        // ---- rescale O, then O += P @ V ----
#pragma unroll
        for (int nf = 0; nf < 16; nf++) {
            O[nf][0] *= f0; O[nf][1] *= f0;
            O[nf][2] *= f1; O[nf][3] *= f1;
        }
#pragma unroll
        for (int kf = 0; kf < 2; kf++) {
            const int kb = kf * 16;
#pragma unroll
            for (int dp = 0; dp < 8; dp++) {
                int boff = (kb + ((lane >> 3) & 1) * 8 + (lane & 7)) * QST
                         + dp*16 + (lane >> 4) * 8;
                uint32_t vbh[4], vbl[4];
                ldsm4t(vbh, smu(&sVh[boff]));
                ldsm4t(vbl, smu(&sVl[boff]));
#pragma unroll
                for (int h2 = 0; h2 < 2; h2++) {
                    float* ac = O[dp*2 + h2];
                    mma16816(ac, pah[kf], &vbh[h2*2]);
                    mma16816(ac, pah[kf], &vbl[h2*2]);
                    mma16816(ac, pal[kf], &vbh[h2*2]);
                }
            }
        }
        __syncthreads();
    }

    // ---- finalize ----
    float i0 = 1.f / l0;
    float i1 = 1.f / l1;
#pragma unroll
    for (int nf = 0; nf < 16; nf++) {
        int col = h*HD + nf*8 + 2*p;
        int row0 = q0 + rbase + g;
        size_t idx0 = (size_t)(b*NN + row0)*DIMM + col;
        uint32_t hi, lo;
        pack2(O[nf][0]*i0, O[nf][1]*i0, hi, lo);
        *(uint32_t*)&aoh[idx0] = hi;
        *(uint32_t*)&aol[idx0] = lo;
        size_t idx1 = (size_t)(b*NN + row0 + 8)*DIMM + col;
        pack2(O[nf][2]*i1, O[nf][3]*i1, hi, lo);
        *(uint32_t*)&aoh[idx1] = hi;
        *(uint32_t*)&aol[idx1] = lo;
    }
}

// ---------------------------------------------------------------------------
extern "C" void kernel_launch(void* const* d_in, const int* in_sizes, int n_in,
                              void* d_out, int out_size)
{
    const float* x     = (const float*)d_in[0];
    const float* ctx   = (const float*)d_in[1];
    const float* dsim  = (const float*)d_in[2];
    const int*   mask  = (const int*)d_in[3];
    const int*   cmask = (const int*)d_in[4];
    const float* Wq    = (const float*)d_in[5];
    const float* Wkv   = (const float*)d_in[6];
    const float* beta  = (const float*)d_in[7];
    const float* Wout  = (const float*)d_in[8];
    const float* bout  = (const float*)d_in[9];
    float* out = (float*)d_out;

    bf16 *xh,*xl,*ch,*cl,*Wqh,*Wql,*Wkvh,*Wkvl,*Woh,*Wol;
    bf16 *qh,*ql,*kh,*kl,*vh,*vl,*aoh,*aol;
    cudaGetSymbolAddress((void**)&xh, g_xh);   cudaGetSymbolAddress((void**)&xl, g_xl);
    cudaGetSymbolAddress((void**)&ch, g_ch);   cudaGetSymbolAddress((void**)&cl, g_cl);
    cudaGetSymbolAddress((void**)&Wqh, g_Wqh); cudaGetSymbolAddress((void**)&Wql, g_Wql);
    cudaGetSymbolAddress((void**)&Wkvh, g_Wkvh); cudaGetSymbolAddress((void**)&Wkvl, g_Wkvl);
    cudaGetSymbolAddress((void**)&Woh, g_Woh); cudaGetSymbolAddress((void**)&Wol, g_Wol);
    cudaGetSymbolAddress((void**)&qh, g_qh);   cudaGetSymbolAddress((void**)&ql, g_ql);
    cudaGetSymbolAddress((void**)&kh, g_kh);   cudaGetSymbolAddress((void**)&kl, g_kl);
    cudaGetSymbolAddress((void**)&vh, g_vh);   cudaGetSymbolAddress((void**)&vl, g_vl);
    cudaGetSymbolAddress((void**)&aoh, g_aoh); cudaGetSymbolAddress((void**)&aol, g_aol);

    cudaFuncSetAttribute(gemm_split<0>, cudaFuncAttributeMaxDynamicSharedMemorySize, GEMM_SMEM);
    cudaFuncSetAttribute(gemm_split<1>, cudaFuncAttributeMaxDynamicSharedMemorySize, GEMM_SMEM);
    cudaFuncSetAttribute(gemm_split<2>, cudaFuncAttributeMaxDynamicSharedMemorySize, GEMM_SMEM);
    cudaFuncSetAttribute(attn_mma, cudaFuncAttributeMaxDynamicSharedMemorySize, ATTN_SMEM);

    // splits
    split_kernel<<<(2048*1024/4)/256, 256>>>(x,   xh,  xl,  2048*1024/4);
    split_kernel<<<(8192*1024/4)/256, 256>>>(ctx, ch,  cl,  8192*1024/4);
    split_kernel<<<(1024*1024/4)/256, 256>>>(Wq,  Wqh, Wql, 1024*1024/4);
    split_kernel<<<(2048*1024/4)/256, 256>>>(Wkv, Wkvh,Wkvl,2048*1024/4);
    split_kernel<<<(1024*1024/4)/256, 256>>>(Wout,Woh, Wol, 1024*1024/4);

    // q = x @ Wq^T  -> q split head-major
    gemm_split<1><<<dim3(1024/TN, 2048/TM), 256, GEMM_SMEM>>>(
        xh, xl, Wqh, Wql, 1024, nullptr, 0, nullptr, qh, ql, nullptr, nullptr);

    // kv = ctx @ Wkv^T -> k,v split head-major
    gemm_split<2><<<dim3(2048/TN, 8192/TM), 256, GEMM_SMEM>>>(
        ch, cl, Wkvh, Wkvl, 1024, nullptr, 0, nullptr, kh, kl, vh, vl);

    // attention (128 threads, 2 CTAs/SM, single wave)
    attn_mma<<<dim3(NN/AQ, HH, BB), 128, ATTN_SMEM>>>(
        qh, ql, kh, kl, vh, vl, dsim, mask, cmask, beta, aoh, aol);

    // out = ao @ Wout^T + bout
    gemm_split<0><<<dim3(1024/TN, 2048/TM), 256, GEMM_SMEM>>>(
        aoh, aol, Woh, Wol, 1024, out, 1024, bout, nullptr, nullptr, nullptr, nullptr);
}